// round 6
// baseline (speedup 1.0000x reference)
#include <cuda_runtime.h>
#include <math.h>

#define D    2048
#define E    64
#define NT   16384      // B*S tokens
#define KC   32         // k-chunk
#define TT   64         // tokens per gemm block
#define SB   128        // tokens per router block
#define NSB  (NT / SB)  // 128 router blocks
#define XS_PAD 68       // 64 + 4, keeps 16B alignment + spreads banks

// ---------------- device scratch (no allocations allowed) ----------------
__device__ float g_logits[(size_t)NT * E];   // 4 MB
__device__ float g_P[NSB * E];
__device__ float g_C[NSB * E];
__device__ float g_Z[NSB];

// ---------------- GEMM: logits[t][e] = sum_d x[t][d] * gw[e][d] ----------
__global__ void __launch_bounds__(256) gemm_kernel(const float* __restrict__ x,
                                                   const float* __restrict__ gw) {
    __shared__ float xs[KC][XS_PAD];   // xs[k][token]
    __shared__ float ws[KC][XS_PAD];   // ws[k][expert]

    const int tid = threadIdx.x;
    const int t0  = blockIdx.x * TT;
    const int tx  = tid & 15;          // expert group (4 experts)
    const int ty  = tid >> 4;          // token group  (4 tokens)
    const int lr  = tid >> 3;          // load row 0..31
    const int lc  = (tid & 7) * 4;     // load col 0,4,...,28

    float acc[4][4];
#pragma unroll
    for (int i = 0; i < 4; i++)
#pragma unroll
        for (int j = 0; j < 4; j++) acc[i][j] = 0.f;

    const float* xr0 = x  + (size_t)(t0 + lr)      * D + lc;
    const float* xr1 = x  + (size_t)(t0 + lr + 32) * D + lc;
    const float* wr0 = gw + (size_t)lr             * D + lc;
    const float* wr1 = gw + (size_t)(lr + 32)      * D + lc;

    for (int kc = 0; kc < D; kc += KC) {
        float4 a0 = *(const float4*)(xr0 + kc);
        float4 a1 = *(const float4*)(xr1 + kc);
        float4 b0 = *(const float4*)(wr0 + kc);
        float4 b1 = *(const float4*)(wr1 + kc);
        __syncthreads();   // previous iteration's readers done
        xs[lc + 0][lr]      = a0.x; xs[lc + 1][lr]      = a0.y;
        xs[lc + 2][lr]      = a0.z; xs[lc + 3][lr]      = a0.w;
        xs[lc + 0][lr + 32] = a1.x; xs[lc + 1][lr + 32] = a1.y;
        xs[lc + 2][lr + 32] = a1.z; xs[lc + 3][lr + 32] = a1.w;
        ws[lc + 0][lr]      = b0.x; ws[lc + 1][lr]      = b0.y;
        ws[lc + 2][lr]      = b0.z; ws[lc + 3][lr]      = b0.w;
        ws[lc + 0][lr + 32] = b1.x; ws[lc + 1][lr + 32] = b1.y;
        ws[lc + 2][lr + 32] = b1.z; ws[lc + 3][lr + 32] = b1.w;
        __syncthreads();
#pragma unroll
        for (int kk = 0; kk < KC; kk++) {
            float4 av = *(const float4*)&xs[kk][ty * 4];
            float4 bv = *(const float4*)&ws[kk][tx * 4];
            acc[0][0] += av.x * bv.x; acc[0][1] += av.x * bv.y;
            acc[0][2] += av.x * bv.z; acc[0][3] += av.x * bv.w;
            acc[1][0] += av.y * bv.x; acc[1][1] += av.y * bv.y;
            acc[1][2] += av.y * bv.z; acc[1][3] += av.y * bv.w;
            acc[2][0] += av.z * bv.x; acc[2][1] += av.z * bv.y;
            acc[2][2] += av.z * bv.z; acc[2][3] += av.z * bv.w;
            acc[3][0] += av.w * bv.x; acc[3][1] += av.w * bv.y;
            acc[3][2] += av.w * bv.z; acc[3][3] += av.w * bv.w;
        }
    }
#pragma unroll
    for (int i = 0; i < 4; i++) {
        float4 o = make_float4(acc[i][0], acc[i][1], acc[i][2], acc[i][3]);
        *(float4*)&g_logits[(size_t)(t0 + ty * 4 + i) * E + tx * 4] = o;
    }
}

// ---------------- Router: softmax + top2 + partial aux -------------------
__global__ void __launch_bounds__(256) router_kernel(float* __restrict__ out) {
    __shared__ float sP[8][64];
    __shared__ int   sC[8][64];
    __shared__ float sZ[8];

    const int tid  = threadIdx.x;
    const int w    = tid >> 5;
    const int lane = tid & 31;

    sC[w][lane] = 0; sC[w][lane + 32] = 0;
    if (lane == 0) sZ[w] = 0.f;
    __syncwarp();

    float p0 = 0.f, p1 = 0.f, zacc = 0.f;
    const int tokBase = blockIdx.x * SB + w * 16;

    for (int it = 0; it < 16; it++) {
        const int tok = tokBase + it;
        const float* lrow = &g_logits[(size_t)tok * E];
        float l0 = lrow[lane];
        float l1 = lrow[lane + 32];

        float m = fmaxf(l0, l1);
#pragma unroll
        for (int o = 16; o > 0; o >>= 1) m = fmaxf(m, __shfl_xor_sync(0xffffffffu, m, o));

        float e0 = expf(l0 - m), e1 = expf(l1 - m);
        float s = e0 + e1;
#pragma unroll
        for (int o = 16; o > 0; o >>= 1) s += __shfl_xor_sync(0xffffffffu, s, o);

        float inv = 1.f / s;
        p0 += e0 * inv;
        p1 += e1 * inv;

        float lse = logf(s) + m;
        zacc += lse * lse;

        // top-1 candidate per lane (tie -> lower index, matching jax top_k)
        float bv; int bi;
        if (e1 > e0) { bv = e1; bi = lane + 32; } else { bv = e0; bi = lane; }
#pragma unroll
        for (int o = 16; o > 0; o >>= 1) {
            float ov = __shfl_xor_sync(0xffffffffu, bv, o);
            int   oi = __shfl_xor_sync(0xffffffffu, bi, o);
            if (ov > bv || (ov == bv && oi < bi)) { bv = ov; bi = oi; }
        }
        // top-2: exclude bi
        float b2; int b2i;
        if (bi == lane)            { b2 = e1; b2i = lane + 32; }
        else if (bi == lane + 32)  { b2 = e0; b2i = lane; }
        else if (e1 > e0)          { b2 = e1; b2i = lane + 32; }
        else                       { b2 = e0; b2i = lane; }
#pragma unroll
        for (int o = 16; o > 0; o >>= 1) {
            float ov = __shfl_xor_sync(0xffffffffu, b2, o);
            int   oi = __shfl_xor_sync(0xffffffffu, b2i, o);
            if (ov > b2 || (ov == b2 && oi < b2i)) { b2 = ov; b2i = oi; }
        }

        if (lane == 0) {
            float sw = bv + b2;
            out[tok * 2 + 0]           = (float)bi;
            out[tok * 2 + 1]           = (float)b2i;
            out[2 * NT + tok * 2 + 0]  = bv / sw;
            out[2 * NT + tok * 2 + 1]  = b2 / sw;
            sC[w][bi]++;
            sC[w][b2i]++;
        }
    }

    sP[w][lane] = p0;
    sP[w][lane + 32] = p1;
    if (lane == 0) sZ[w] = zacc;
    __syncthreads();

    if (tid < 64) {
        float ps = 0.f, cs = 0.f;
#pragma unroll
        for (int ww = 0; ww < 8; ww++) {
            ps += sP[ww][tid];
            cs += (float)sC[ww][tid];
        }
        g_P[blockIdx.x * E + tid] = ps;
        g_C[blockIdx.x * E + tid] = cs;
    }
    if (tid == 64) {
        float z = 0.f;
#pragma unroll
        for (int ww = 0; ww < 8; ww++) z += sZ[ww];
        g_Z[blockIdx.x] = z;
    }
}

// ---------------- Finalize aux loss --------------------------------------
__global__ void __launch_bounds__(64) finalize_kernel(float* __restrict__ out) {
    __shared__ float red[64];
    const int tid = threadIdx.x;   // 64 threads, one per expert
    float P = 0.f, C = 0.f;
    for (int b = 0; b < NSB; b++) {
        P += g_P[b * E + tid];
        C += g_C[b * E + tid];
    }
    float f  = C / (float)(NT * 2);
    float Pm = P / (float)NT;
    red[tid] = f * Pm;
    __syncthreads();
    for (int o = 32; o > 0; o >>= 1) {
        if (tid < o) red[tid] += red[tid + o];
        __syncthreads();
    }
    if (tid == 0) {
        float z = 0.f;
        for (int b = 0; b < NSB; b++) z += g_Z[b];
        float balance = (float)E * red[0];
        float zmean   = z / (float)NT;
        out[4 * NT] = 0.01f * balance + 0.001f * zmean;
    }
}

// ---------------- launch --------------------------------------------------
extern "C" void kernel_launch(void* const* d_in, const int* in_sizes, int n_in,
                              void* d_out, int out_size) {
    const float* x  = (const float*)d_in[0];
    const float* gw = (const float*)d_in[1];
    float* out = (float*)d_out;

    gemm_kernel<<<NT / TT, 256>>>(x, gw);
    router_kernel<<<NT / SB, 256>>>(out);
    finalize_kernel<<<1, 64>>>(out);
}